// round 11
// baseline (speedup 1.0000x reference)
#include <cuda_runtime.h>
#include <stdint.h>

#define NLV 16
#define LOG2T 19
#define TSIZE (1u << LOG2T)
#define TMASK (TSIZE - 1u)
#define BASE_RES 16

#define N_MAX (1 << 20)
#define BIN_BITS_AXIS 6
#define NBINS (1 << (3 * BIN_BITS_AXIS))   // 262144
#define SCAN_B 256
#define SCAN_NB (NBINS / SCAN_B)           // 1024

// ---------------- scratch (static device memory; no allocs) ----------------
__device__ float    g_norm[6];              // [0..2]=bb_min, [3..5]=1/(ext)
__device__ float4   g_xs[N_MAX];            // sorted normalized positions
__device__ uint32_t g_perm[N_MAX];          // sorted -> original index
__device__ uint32_t g_rank[N_MAX];          // rank within bin (from hist pass)
__device__ uint32_t g_hist[NBINS];          // counts
__device__ uint32_t g_off[NBINS];           // exclusive offsets
__device__ uint32_t g_bsum[SCAN_NB];        // per-scan-block sums
__device__ uint32_t g_bpref[SCAN_NB];       // exclusive prefix of block sums

// ---------------- helpers ----------------
__device__ __forceinline__ uint32_t expand3(uint32_t v)
{
    v &= 63u;
    v = (v | (v << 8)) & 0x300Fu;
    v = (v | (v << 4)) & 0x30C3u;
    v = (v | (v << 2)) & 0x9249u;
    return v;
}

__device__ __forceinline__ uint32_t morton_key(float xnx, float xny, float xnz)
{
    const float s = (float)(1 << BIN_BITS_AXIS);
    int ix = (int)(xnx * s), iy = (int)(xny * s), iz = (int)(xnz * s);
    const int mx = (1 << BIN_BITS_AXIS) - 1;
    ix = min(mx, max(0, ix)); iy = min(mx, max(0, iy)); iz = min(mx, max(0, iz));
    return expand3((uint32_t)ix) | (expand3((uint32_t)iy) << 1) | (expand3((uint32_t)iz) << 2);
}

// one level's trilinear-hash encode (PRIME_x==1 pair-merge version)
__device__ __forceinline__ void level_encode(
    float xnx, float xny, float xnz, int l,
    const float* __restrict__ table, float& f0, float& f1)
{
    const float resf = (float)(BASE_RES << l);
    const float posx = xnx * resf;
    const float posy = xny * resf;
    const float posz = xnz * resf;
    const float flx = floorf(posx);
    const float fly = floorf(posy);
    const float flz = floorf(posz);
    const float fx = posx - flx;
    const float fy = posy - fly;
    const float fz = posz - flz;

    const uint32_t ux = (uint32_t)(int32_t)flx;
    const uint32_t uy = (uint32_t)(int32_t)fly;
    const uint32_t uz = (uint32_t)(int32_t)flz;

    const uint32_t hy0 = uy * 2654435761u;
    const uint32_t hy1 = (uy + 1u) * 2654435761u;
    const uint32_t hz0 = uz * 805459861u;
    const uint32_t hz1 = (uz + 1u) * 805459861u;

    const float2* __restrict__ tbl2 = (const float2*)table + (size_t)l * TSIZE;
    const float4* __restrict__ tbl4 = (const float4*)tbl2;

    const uint32_t e00 = (ux ^ hy0 ^ hz0) & TMASK;
    const uint32_t e01 = (ux ^ hy0 ^ hz1) & TMASK;
    const uint32_t e10 = (ux ^ hy1 ^ hz0) & TMASK;
    const uint32_t e11 = (ux ^ hy1 ^ hz1) & TMASK;
    const uint32_t ux1 = ux + 1u;
    const uint32_t f00i = (ux1 ^ hy0 ^ hz0) & TMASK;
    const uint32_t f01i = (ux1 ^ hy0 ^ hz1) & TMASK;
    const uint32_t f10i = (ux1 ^ hy1 ^ hz0) & TMASK;
    const uint32_t f11i = (ux1 ^ hy1 ^ hz1) & TMASK;

    const bool ux_odd = (ux & 1u) != 0u;

    const float4 q00 = __ldg(tbl4 + (e00 >> 1));
    const float4 q01 = __ldg(tbl4 + (e01 >> 1));
    const float4 q10 = __ldg(tbl4 + (e10 >> 1));
    const float4 q11 = __ldg(tbl4 + (e11 >> 1));

    float2 d00, d01, d10, d11;
    if (ux_odd) {
        d00 = __ldg(tbl2 + f00i);
        d01 = __ldg(tbl2 + f01i);
        d10 = __ldg(tbl2 + f10i);
        d11 = __ldg(tbl2 + f11i);
    }

    const bool h00 = (e00 & 1u), h01 = (e01 & 1u), h10 = (e10 & 1u), h11 = (e11 & 1u);

    const float2 c000 = h00 ? make_float2(q00.z, q00.w) : make_float2(q00.x, q00.y);
    const float2 c001 = h01 ? make_float2(q01.z, q01.w) : make_float2(q01.x, q01.y);
    const float2 c010 = h10 ? make_float2(q10.z, q10.w) : make_float2(q10.x, q10.y);
    const float2 c011 = h11 ? make_float2(q11.z, q11.w) : make_float2(q11.x, q11.y);

    float2 c100 = h00 ? make_float2(q00.x, q00.y) : make_float2(q00.z, q00.w);
    float2 c101 = h01 ? make_float2(q01.x, q01.y) : make_float2(q01.z, q01.w);
    float2 c110 = h10 ? make_float2(q10.x, q10.y) : make_float2(q10.z, q10.w);
    float2 c111 = h11 ? make_float2(q11.x, q11.y) : make_float2(q11.z, q11.w);
    if (ux_odd) { c100 = d00; c101 = d01; c110 = d10; c111 = d11; }

    const float wx1 = fx, wx0 = 1.f - fx;
    const float wy1 = fy, wy0 = 1.f - fy;
    const float wz1 = fz, wz0 = 1.f - fz;

    float a0 = 0.f, a1 = 0.f, w;
    w = wx0 * wy0 * wz0; a0 += w * c000.x; a1 += w * c000.y;
    w = wx0 * wy0 * wz1; a0 += w * c001.x; a1 += w * c001.y;
    w = wx0 * wy1 * wz0; a0 += w * c010.x; a1 += w * c010.y;
    w = wx0 * wy1 * wz1; a0 += w * c011.x; a1 += w * c011.y;
    w = wx1 * wy0 * wz0; a0 += w * c100.x; a1 += w * c100.y;
    w = wx1 * wy0 * wz1; a0 += w * c101.x; a1 += w * c101.y;
    w = wx1 * wy1 * wz0; a0 += w * c110.x; a1 += w * c110.y;
    w = wx1 * wy1 * wz1; a0 += w * c111.x; a1 += w * c111.y;
    f0 = a0; f1 = a1;
}

// ---------------- pipeline kernels ----------------
__global__ void prep_kernel(const float* __restrict__ bb)
{
    if (threadIdx.x == 0) {
        #pragma unroll
        for (int i = 0; i < 3; ++i) {
            g_norm[i]     = bb[i];
            g_norm[3 + i] = 1.0f / (bb[3 + i] - bb[i]);
        }
    }
}

__global__ void zero_hist_kernel()
{
    const int i = blockIdx.x * blockDim.x + threadIdx.x;
    if (i < NBINS) g_hist[i] = 0u;
}

// mask + morton histogram; stores per-point rank within its bin
__global__ void hist_kernel(const float* __restrict__ x, float* __restrict__ mask_out, int n)
{
    const int i = blockIdx.x * blockDim.x + threadIdx.x;
    if (i >= n) return;
    const float xnx = (x[i * 3 + 0] - g_norm[0]) * g_norm[3];
    const float xny = (x[i * 3 + 1] - g_norm[1]) * g_norm[4];
    const float xnz = (x[i * 3 + 2] - g_norm[2]) * g_norm[5];
    const bool m = (xnx > 0.f) & (xnx < 1.f) &
                   (xny > 0.f) & (xny < 1.f) &
                   (xnz > 0.f) & (xnz < 1.f);
    mask_out[i] = m ? 1.0f : 0.0f;
    const uint32_t key = morton_key(xnx, xny, xnz);
    g_rank[i] = atomicAdd(&g_hist[key], 1u);
}

// scan stage A: per-block (256 bins) sums
__global__ void scanA_kernel()
{
    __shared__ uint32_t sm[SCAN_B];
    const int b = blockIdx.x, t = threadIdx.x;
    sm[t] = g_hist[b * SCAN_B + t];
    __syncthreads();
    #pragma unroll
    for (int off = SCAN_B / 2; off > 0; off >>= 1) {
        if (t < off) sm[t] += sm[t + off];
        __syncthreads();
    }
    if (t == 0) g_bsum[b] = sm[0];
}

// scan stage B: exclusive scan of the 1024 block sums (one block)
__global__ void scanB_kernel()
{
    __shared__ uint32_t sm[SCAN_NB];
    const int t = threadIdx.x;
    sm[t] = g_bsum[t];
    __syncthreads();
    #pragma unroll
    for (int off = 1; off < SCAN_NB; off <<= 1) {
        const uint32_t v = (t >= off) ? sm[t - off] : 0u;
        __syncthreads();
        sm[t] += v;
        __syncthreads();
    }
    g_bpref[t] = (t == 0) ? 0u : sm[t - 1];
}

// scan stage C: per-bin exclusive offsets = block prefix + intra-block exclusive
__global__ void scanC_kernel()
{
    __shared__ uint32_t sm[SCAN_B];
    const int b = blockIdx.x, t = threadIdx.x;
    const uint32_t c = g_hist[b * SCAN_B + t];
    sm[t] = c;
    __syncthreads();
    #pragma unroll
    for (int off = 1; off < SCAN_B; off <<= 1) {
        const uint32_t v = (t >= off) ? sm[t - off] : 0u;
        __syncthreads();
        sm[t] += v;
        __syncthreads();
    }
    g_off[b * SCAN_B + t] = g_bpref[b] + sm[t] - c;
}

// scatter: pos = off[key] + rank; write sorted normalized pos + permutation
__global__ void scatter_kernel(const float* __restrict__ x, int n)
{
    const int i = blockIdx.x * blockDim.x + threadIdx.x;
    if (i >= n) return;
    const float xnx = (x[i * 3 + 0] - g_norm[0]) * g_norm[3];
    const float xny = (x[i * 3 + 1] - g_norm[1]) * g_norm[4];
    const float xnz = (x[i * 3 + 2] - g_norm[2]) * g_norm[5];
    const uint32_t key = morton_key(xnx, xny, xnz);
    const uint32_t pos = g_off[key] + g_rank[i];
    g_xs[pos] = make_float4(xnx, xny, xnz, 0.f);
    g_perm[pos] = (uint32_t)i;
}

// main: block = 32 sorted points x 16 levels; warp = one level x 32 adjacent points
#define BLKM 512
__global__ __launch_bounds__(BLKM) void hash_enc_sorted_kernel(
    const float* __restrict__ table,
    float* __restrict__ out,
    int n)
{
    __shared__ __align__(16) float s[32 * 36];
    __shared__ uint32_t so[32];

    const int lane = threadIdx.x & 31;      // point within block
    const int lvl  = threadIdx.x >> 5;      // level (warp id)
    const long ps  = (long)blockIdx.x * 32 + lane;
    const bool act = ps < n;

    float f0 = 0.f, f1 = 0.f;
    if (act) {
        const float4 xs = g_xs[ps];         // coalesced float4 read, no sync needed
        if (lvl == 0) so[lane] = g_perm[ps];
        level_encode(xs.x, xs.y, xs.z, lvl, table, f0, f1);
    }
    s[lane * 36 + 2 * lvl + 0] = f0;
    s[lane * 36 + 2 * lvl + 1] = f1;
    __syncthreads();

    // write 32 rows x 128B, each row contiguous at its original index
    if (threadIdx.x < 256) {
        const int p = threadIdx.x >> 3;
        const int c = threadIdx.x & 7;
        const long gp = (long)blockIdx.x * 32 + p;
        if (gp < n) {
            const float4 v = *(const float4*)&s[p * 36 + c * 4];
            ((float4*)out)[(size_t)so[p] * 8 + c] = v;
        }
    }
}

// ---------------- fallback (n > N_MAX): R5 kernel ----------------
#define BLKF 256
#define PTS_PER_BLKF (BLKF / NLV)
__global__ __launch_bounds__(BLKF) void hash_enc_lvlpar_kernel(
    const float* __restrict__ x,
    const float* __restrict__ table,
    float* __restrict__ out,
    float* __restrict__ mask_out,
    int n)
{
    const int tid = threadIdx.x;
    const int l = tid & (NLV - 1);
    const int pl = tid >> 4;
    const long pt = (long)blockIdx.x * PTS_PER_BLKF + pl;
    if (pt >= n) return;

    const float xnx = (__ldg(x + pt * 3 + 0) - g_norm[0]) * g_norm[3];
    const float xny = (__ldg(x + pt * 3 + 1) - g_norm[1]) * g_norm[4];
    const float xnz = (__ldg(x + pt * 3 + 2) - g_norm[2]) * g_norm[5];

    if (l == 0) {
        const bool m = (xnx > 0.f) & (xnx < 1.f) &
                       (xny > 0.f) & (xny < 1.f) &
                       (xnz > 0.f) & (xnz < 1.f);
        mask_out[pt] = m ? 1.0f : 0.0f;
    }
    float f0, f1;
    level_encode(xnx, xny, xnz, l, table, f0, f1);
    ((float2*)out)[pt * NLV + l] = make_float2(f0, f1);
}

// ---------------- launch ----------------
extern "C" void kernel_launch(void* const* d_in, const int* in_sizes, int n_in,
                              void* d_out, int out_size)
{
    const float* x     = (const float*)d_in[0];   // [N,3]
    const float* bb    = (const float*)d_in[1];   // [6]
    const float* table = (const float*)d_in[2];   // [16, 2^19, 2]

    const int n = in_sizes[0] / 3;
    float* out = (float*)d_out;
    float* mask_out = out + (size_t)n * 32;       // enc [N,32] then mask [N]

    prep_kernel<<<1, 32>>>(bb);

    if (n <= N_MAX) {
        zero_hist_kernel<<<NBINS / 256, 256>>>();
        hist_kernel<<<(n + 255) / 256, 256>>>(x, mask_out, n);
        scanA_kernel<<<SCAN_NB, SCAN_B>>>();
        scanB_kernel<<<1, SCAN_NB>>>();
        scanC_kernel<<<SCAN_NB, SCAN_B>>>();
        scatter_kernel<<<(n + 255) / 256, 256>>>(x, n);
        hash_enc_sorted_kernel<<<(n + 31) / 32, BLKM>>>(table, out, n);
    } else {
        const int grid = (n + PTS_PER_BLKF - 1) / PTS_PER_BLKF;
        hash_enc_lvlpar_kernel<<<grid, BLKF>>>(x, table, out, mask_out, n);
    }
}

// round 12
// speedup vs baseline: 1.2026x; 1.2026x over previous
#include <cuda_runtime.h>
#include <stdint.h>

#define NLV 16
#define LOG2T 19
#define TSIZE (1u << LOG2T)
#define TMASK (TSIZE - 1u)
#define BASE_RES 16
#define BLK 256            // 16 points x 16 levels per block
#define PTS_PER_BLK (BLK / NLV)

// precomputed normalization: [0..2]=bb_min, [3..5]=1/(bb_max-bb_min)
__device__ float g_norm[6];

__global__ void prep_kernel(const float* __restrict__ bb)
{
    if (threadIdx.x == 0) {
        #pragma unroll
        for (int i = 0; i < 3; ++i) {
            g_norm[i]     = bb[i];
            g_norm[3 + i] = 1.0f / (bb[3 + i] - bb[i]);
        }
    }
}

__global__ __launch_bounds__(BLK, 7) void hash_enc_lvlpar_kernel(
    const float* __restrict__ x,
    const float* __restrict__ table,
    float* __restrict__ out,
    float* __restrict__ mask_out,
    int n)
{
    const int tid = threadIdx.x;
    const int l = tid & (NLV - 1);          // level
    const int pl = tid >> 4;                // local point index (0..15)
    const long pt = (long)blockIdx.x * PTS_PER_BLK + pl;
    if (pt >= n) return;

    const float bx0 = g_norm[0], by0 = g_norm[1], bz0 = g_norm[2];
    const float ix  = g_norm[3], iy  = g_norm[4], iz  = g_norm[5];

    const float px = __ldg(x + pt * 3 + 0);
    const float py = __ldg(x + pt * 3 + 1);
    const float pz = __ldg(x + pt * 3 + 2);
    const float xnx = (px - bx0) * ix;
    const float xny = (py - by0) * iy;
    const float xnz = (pz - bz0) * iz;

    if (l == 0) {
        const bool m = (xnx > 0.f) & (xnx < 1.f) &
                       (xny > 0.f) & (xny < 1.f) &
                       (xnz > 0.f) & (xnz < 1.f);
        mask_out[pt] = m ? 1.0f : 0.0f;
    }

    // level resolution: floor(16 * 2^l) == 16 << l (exact in fp32)
    const float resf = (float)(BASE_RES << l);
    const float posx = xnx * resf;
    const float posy = xny * resf;
    const float posz = xnz * resf;
    const float flx = floorf(posx);
    const float fly = floorf(posy);
    const float flz = floorf(posz);
    const float fx = posx - flx;
    const float fy = posy - fly;
    const float fz = posz - flz;

    const uint32_t ux = (uint32_t)(int32_t)flx;
    const uint32_t uy = (uint32_t)(int32_t)fly;
    const uint32_t uz = (uint32_t)(int32_t)flz;

    // per-axis hash contributions: h = x*1 ^ y*P1 ^ z*P2 (uint32 wrap)
    const uint32_t hy0 = uy * 2654435761u;
    const uint32_t hy1 = (uy + 1u) * 2654435761u;
    const uint32_t hz0 = uz * 805459861u;
    const uint32_t hz1 = (uz + 1u) * 805459861u;

    const float2* __restrict__ tbl2 = (const float2*)table + (size_t)l * TSIZE;
    const float4* __restrict__ tbl4 = (const float4*)tbl2;

    // x0-corner indices for the 4 (y,z) combos
    const uint32_t e00 = (ux ^ hy0 ^ hz0) & TMASK;
    const uint32_t e01 = (ux ^ hy0 ^ hz1) & TMASK;
    const uint32_t e10 = (ux ^ hy1 ^ hz0) & TMASK;
    const uint32_t e11 = (ux ^ hy1 ^ hz1) & TMASK;
    // x1-corner indices (distinct line only when ux is odd)
    const uint32_t ux1 = ux + 1u;
    const uint32_t f00 = (ux1 ^ hy0 ^ hz0) & TMASK;
    const uint32_t f01 = (ux1 ^ hy0 ^ hz1) & TMASK;
    const uint32_t f10 = (ux1 ^ hy1 ^ hz0) & TMASK;
    const uint32_t f11 = (ux1 ^ hy1 ^ hz1) & TMASK;

    const bool ux_odd = (ux & 1u) != 0u;

    // 4 paired gathers: float4 at (e>>1) covers {e&~1, e|1}; when ux even the
    // x1 corner IS e^1 (PRIME_x == 1), so one load serves both x-corners.
    const float4 q00 = __ldg(tbl4 + (e00 >> 1));
    const float4 q01 = __ldg(tbl4 + (e01 >> 1));
    const float4 q10 = __ldg(tbl4 + (e10 >> 1));
    const float4 q11 = __ldg(tbl4 + (e11 >> 1));

    // predicated extra gathers for odd ux (x1 corner not adjacent then)
    float2 d00, d01, d10, d11;
    if (ux_odd) {
        d00 = __ldg(tbl2 + f00);
        d01 = __ldg(tbl2 + f01);
        d10 = __ldg(tbl2 + f10);
        d11 = __ldg(tbl2 + f11);
    }

    const bool h00 = (e00 & 1u), h01 = (e01 & 1u), h10 = (e10 & 1u), h11 = (e11 & 1u);

    // x0 corners: select proper half of the float4
    const float2 c000 = h00 ? make_float2(q00.z, q00.w) : make_float2(q00.x, q00.y);
    const float2 c001 = h01 ? make_float2(q01.z, q01.w) : make_float2(q01.x, q01.y);
    const float2 c010 = h10 ? make_float2(q10.z, q10.w) : make_float2(q10.x, q10.y);
    const float2 c011 = h11 ? make_float2(q11.z, q11.w) : make_float2(q11.x, q11.y);

    // x1 corners: other half when even, separate load when odd
    float2 c100 = h00 ? make_float2(q00.x, q00.y) : make_float2(q00.z, q00.w);
    float2 c101 = h01 ? make_float2(q01.x, q01.y) : make_float2(q01.z, q01.w);
    float2 c110 = h10 ? make_float2(q10.x, q10.y) : make_float2(q10.z, q10.w);
    float2 c111 = h11 ? make_float2(q11.x, q11.y) : make_float2(q11.z, q11.w);
    if (ux_odd) { c100 = d00; c101 = d01; c110 = d10; c111 = d11; }

    const float wx1 = fx, wx0 = 1.f - fx;
    const float wy1 = fy, wy0 = 1.f - fy;
    const float wz1 = fz, wz0 = 1.f - fz;

    float f0 = 0.f, f1 = 0.f, w;
    w = wx0 * wy0 * wz0; f0 += w * c000.x; f1 += w * c000.y;
    w = wx0 * wy0 * wz1; f0 += w * c001.x; f1 += w * c001.y;
    w = wx0 * wy1 * wz0; f0 += w * c010.x; f1 += w * c010.y;
    w = wx0 * wy1 * wz1; f0 += w * c011.x; f1 += w * c011.y;
    w = wx1 * wy0 * wz0; f0 += w * c100.x; f1 += w * c100.y;
    w = wx1 * wy0 * wz1; f0 += w * c101.x; f1 += w * c101.y;
    w = wx1 * wy1 * wz0; f0 += w * c110.x; f1 += w * c110.y;
    w = wx1 * wy1 * wz1; f0 += w * c111.x; f1 += w * c111.y;

    // enc[pt][2*l .. 2*l+1] — consecutive lanes write consecutive float2s (coalesced)
    float2* __restrict__ out2 = (float2*)out;
    out2[pt * NLV + l] = make_float2(f0, f1);
}

extern "C" void kernel_launch(void* const* d_in, const int* in_sizes, int n_in,
                              void* d_out, int out_size)
{
    const float* x     = (const float*)d_in[0];   // [N,3]
    const float* bb    = (const float*)d_in[1];   // [6]
    const float* table = (const float*)d_in[2];   // [16, 2^19, 2]

    const int n = in_sizes[0] / 3;
    float* out = (float*)d_out;
    float* mask_out = out + (size_t)n * 32;       // enc [N,32] then mask [N]

    prep_kernel<<<1, 32>>>(bb);

    const int grid = (n + PTS_PER_BLK - 1) / PTS_PER_BLK;
    hash_enc_lvlpar_kernel<<<grid, BLK>>>(x, table, out, mask_out, n);
}

// round 13
// speedup vs baseline: 1.5009x; 1.2481x over previous
#include <cuda_runtime.h>
#include <stdint.h>

#define NLV 16
#define LOG2T 19
#define TSIZE (1u << LOG2T)
#define TMASK (TSIZE - 1u)
#define BASE_RES 16
#define BLK 256            // 16 points x 16 levels per block
#define PTS_PER_BLK (BLK / NLV)

// precomputed normalization: [0..2]=bb_min, [3..5]=1/(bb_max-bb_min)
__device__ float g_norm[6];

__global__ void prep_kernel(const float* __restrict__ bb)
{
    if (threadIdx.x == 0) {
        #pragma unroll
        for (int i = 0; i < 3; ++i) {
            g_norm[i]     = bb[i];
            g_norm[3 + i] = 1.0f / (bb[3 + i] - bb[i]);
        }
    }
}

__global__ __launch_bounds__(BLK) void hash_enc_lvlpar_kernel(
    const float* __restrict__ x,
    const float* __restrict__ table,
    float* __restrict__ out,
    float* __restrict__ mask_out,
    int n)
{
    const int tid = threadIdx.x;
    const int l = tid & (NLV - 1);          // level
    const int pl = tid >> 4;                // local point index (0..15)
    const long pt = (long)blockIdx.x * PTS_PER_BLK + pl;
    if (pt >= n) return;

    const float bx0 = g_norm[0], by0 = g_norm[1], bz0 = g_norm[2];
    const float ix  = g_norm[3], iy  = g_norm[4], iz  = g_norm[5];

    const float px = __ldg(x + pt * 3 + 0);
    const float py = __ldg(x + pt * 3 + 1);
    const float pz = __ldg(x + pt * 3 + 2);
    const float xnx = (px - bx0) * ix;
    const float xny = (py - by0) * iy;
    const float xnz = (pz - bz0) * iz;

    if (l == 0) {
        const bool m = (xnx > 0.f) & (xnx < 1.f) &
                       (xny > 0.f) & (xny < 1.f) &
                       (xnz > 0.f) & (xnz < 1.f);
        mask_out[pt] = m ? 1.0f : 0.0f;
    }

    // level resolution: floor(16 * 2^l) == 16 << l (exact in fp32)
    const float resf = (float)(BASE_RES << l);
    const float posx = xnx * resf;
    const float posy = xny * resf;
    const float posz = xnz * resf;
    const float flx = floorf(posx);
    const float fly = floorf(posy);
    const float flz = floorf(posz);
    const float fx = posx - flx;
    const float fy = posy - fly;
    const float fz = posz - flz;

    const uint32_t ux = (uint32_t)(int32_t)flx;
    const uint32_t uy = (uint32_t)(int32_t)fly;
    const uint32_t uz = (uint32_t)(int32_t)flz;

    // per-axis hash contributions: h = x*1 ^ y*P1 ^ z*P2 (uint32 wrap)
    const uint32_t hy0 = uy * 2654435761u;
    const uint32_t hy1 = (uy + 1u) * 2654435761u;
    const uint32_t hz0 = uz * 805459861u;
    const uint32_t hz1 = (uz + 1u) * 805459861u;

    const float2* __restrict__ tbl2 = (const float2*)table + (size_t)l * TSIZE;
    const float4* __restrict__ tbl4 = (const float4*)tbl2;

    // x0-corner indices for the 4 (y,z) combos
    const uint32_t e00 = (ux ^ hy0 ^ hz0) & TMASK;
    const uint32_t e01 = (ux ^ hy0 ^ hz1) & TMASK;
    const uint32_t e10 = (ux ^ hy1 ^ hz0) & TMASK;
    const uint32_t e11 = (ux ^ hy1 ^ hz1) & TMASK;
    // x1-corner indices (distinct cache line only when ux is odd)
    const uint32_t ux1 = ux + 1u;
    const uint32_t f00 = (ux1 ^ hy0 ^ hz0) & TMASK;
    const uint32_t f01 = (ux1 ^ hy0 ^ hz1) & TMASK;
    const uint32_t f10 = (ux1 ^ hy1 ^ hz0) & TMASK;
    const uint32_t f11 = (ux1 ^ hy1 ^ hz1) & TMASK;

    const bool ux_odd = (ux & 1u) != 0u;

    // 4 paired gathers: float4 at (e>>1) covers entries {e&~1, e|1}; when ux
    // is even the x1 corner IS e^1 (PRIME_x == 1) -> one load, both corners.
    const float4 q00 = __ldg(tbl4 + (e00 >> 1));
    const float4 q01 = __ldg(tbl4 + (e01 >> 1));
    const float4 q10 = __ldg(tbl4 + (e10 >> 1));
    const float4 q11 = __ldg(tbl4 + (e11 >> 1));

    // predicated extra gathers for odd ux (x1 corners not adjacent then)
    float2 d00, d01, d10, d11;
    if (ux_odd) {
        d00 = __ldg(tbl2 + f00);
        d01 = __ldg(tbl2 + f01);
        d10 = __ldg(tbl2 + f10);
        d11 = __ldg(tbl2 + f11);
    }

    const bool h00 = (e00 & 1u), h01 = (e01 & 1u), h10 = (e10 & 1u), h11 = (e11 & 1u);

    // x0 corners: select proper half of the float4
    const float2 c000 = h00 ? make_float2(q00.z, q00.w) : make_float2(q00.x, q00.y);
    const float2 c001 = h01 ? make_float2(q01.z, q01.w) : make_float2(q01.x, q01.y);
    const float2 c010 = h10 ? make_float2(q10.z, q10.w) : make_float2(q10.x, q10.y);
    const float2 c011 = h11 ? make_float2(q11.z, q11.w) : make_float2(q11.x, q11.y);

    // x1 corners: other half when even, separate load when odd
    float2 c100 = h00 ? make_float2(q00.x, q00.y) : make_float2(q00.z, q00.w);
    float2 c101 = h01 ? make_float2(q01.x, q01.y) : make_float2(q01.z, q01.w);
    float2 c110 = h10 ? make_float2(q10.x, q10.y) : make_float2(q10.z, q10.w);
    float2 c111 = h11 ? make_float2(q11.x, q11.y) : make_float2(q11.z, q11.w);
    if (ux_odd) { c100 = d00; c101 = d01; c110 = d10; c111 = d11; }

    const float wx1 = fx, wx0 = 1.f - fx;
    const float wy1 = fy, wy0 = 1.f - fy;
    const float wz1 = fz, wz0 = 1.f - fz;

    float f0 = 0.f, f1 = 0.f, w;
    w = wx0 * wy0 * wz0; f0 += w * c000.x; f1 += w * c000.y;
    w = wx0 * wy0 * wz1; f0 += w * c001.x; f1 += w * c001.y;
    w = wx0 * wy1 * wz0; f0 += w * c010.x; f1 += w * c010.y;
    w = wx0 * wy1 * wz1; f0 += w * c011.x; f1 += w * c011.y;
    w = wx1 * wy0 * wz0; f0 += w * c100.x; f1 += w * c100.y;
    w = wx1 * wy0 * wz1; f0 += w * c101.x; f1 += w * c101.y;
    w = wx1 * wy1 * wz0; f0 += w * c110.x; f1 += w * c110.y;
    w = wx1 * wy1 * wz1; f0 += w * c111.x; f1 += w * c111.y;

    // enc[pt][2*l .. 2*l+1] — consecutive lanes write consecutive float2s (coalesced)
    float2* __restrict__ out2 = (float2*)out;
    out2[pt * NLV + l] = make_float2(f0, f1);
}

extern "C" void kernel_launch(void* const* d_in, const int* in_sizes, int n_in,
                              void* d_out, int out_size)
{
    const float* x     = (const float*)d_in[0];   // [N,3]
    const float* bb    = (const float*)d_in[1];   // [6]
    const float* table = (const float*)d_in[2];   // [16, 2^19, 2]

    const int n = in_sizes[0] / 3;
    float* out = (float*)d_out;
    float* mask_out = out + (size_t)n * 32;       // enc [N,32] then mask [N]

    prep_kernel<<<1, 32>>>(bb);

    const int grid = (n + PTS_PER_BLK - 1) / PTS_PER_BLK;
    hash_enc_lvlpar_kernel<<<grid, BLK>>>(x, table, out, mask_out, n);
}